// round 9
// baseline (speedup 1.0000x reference)
#include <cuda_runtime.h>
#include <math.h>
#include <stdint.h>

#define N_NODES 20000
#define E_EDGES 320000
#define EN      340000   // E + N self loops
#define IN_DIM  256
#define HID     64
#define NH      4
#define CD      64
#define HC      256      // NH*CD
#define DFF     128
#define NL      4

#define SCAN_NB 79       // ceil(20000/256)

// ---------------- scratch (module-global device memory; no runtime alloc) ----
__device__ __align__(16) float g_xh[N_NODES * HC];      // f2 buffer / aggregated-h buffer
__device__ __align__(16) float g_as[N_NODES * NH];      // attention src scores
__device__ __align__(16) float g_ad[N_NODES * NH];      // attention dst scores
__device__ __align__(16) float g_watt[NL * HID * 8];    // per-layer ws_hat/wd_hat
__device__ int   g_srt_src[EN];
__device__ int   g_cnt[N_NODES];
__device__ int   g_off[N_NODES + 1];
__device__ int   g_cur[N_NODES];
__device__ int   g_bsum[SCAN_NB];
__device__ int   g_bpre[SCAN_NB];
__device__ __align__(16) float g_out[N_NODES * HC];     // projected messages
__device__ __align__(16) float g_f1[N_NODES * DFF];     // FFN hidden

// ---------------- CSR build ----------------
__global__ void zero_cnt_kernel() {
    int i = blockIdx.x * blockDim.x + threadIdx.x;
    if (i < N_NODES) g_cnt[i] = 0;
}

__global__ void hist_kernel(const int* __restrict__ ei) {
    int i = blockIdx.x * blockDim.x + threadIdx.x;
    if (i >= EN) return;
    int d = (i < E_EDGES) ? ei[E_EDGES + i] : (i - E_EDGES);
    atomicAdd(&g_cnt[d], 1);
}

// phase 1: per-block exclusive scan of 256 counts; block total -> g_bsum
__global__ __launch_bounds__(256) void scan1_kernel() {
    __shared__ int ws[8];
    int t = threadIdx.x, b = blockIdx.x;
    int i = b * 256 + t;
    int v = (i < N_NODES) ? g_cnt[i] : 0;
    int lane = t & 31, w = t >> 5;
    int x = v;
#pragma unroll
    for (int o = 1; o < 32; o <<= 1) {
        int y = __shfl_up_sync(0xffffffffu, x, o);
        if (lane >= o) x += y;
    }
    if (lane == 31) ws[w] = x;
    __syncthreads();
    if (t < 8) {
        int y = ws[t];
#pragma unroll
        for (int o = 1; o < 8; o <<= 1) {
            int z = __shfl_up_sync(0xffu, y, o);
            if (t >= o) y += z;
        }
        ws[t] = y;
    }
    __syncthreads();
    int incl = x + (w > 0 ? ws[w - 1] : 0);
    int excl = incl - v;
    if (i < N_NODES) g_off[i] = excl;
    if (t == 255) g_bsum[b] = incl;
}

// phase 2: scan the 79 block sums (single block)
__global__ void scan2_kernel() {
    __shared__ int s[128];
    int t = threadIdx.x;
    s[t] = (t < SCAN_NB) ? g_bsum[t] : 0;
    __syncthreads();
#pragma unroll
    for (int o = 1; o < 128; o <<= 1) {
        int v = (t >= o) ? s[t - o] : 0;
        __syncthreads();
        s[t] += v;
        __syncthreads();
    }
    if (t < SCAN_NB) g_bpre[t] = (t > 0) ? s[t - 1] : 0;
}

// phase 3: add block prefix, fill g_cur, set sentinel
__global__ __launch_bounds__(256) void scan3_kernel() {
    int t = threadIdx.x, b = blockIdx.x;
    int i = b * 256 + t;
    if (i < N_NODES) {
        int v = g_off[i] + g_bpre[b];
        g_off[i] = v;
        g_cur[i] = v;
    }
    if (i == 0) g_off[N_NODES] = EN;
}

__global__ void scatter_kernel(const int* __restrict__ ei) {
    int i = blockIdx.x * blockDim.x + threadIdx.x;
    if (i >= EN) return;
    int s, d;
    if (i < E_EDGES) { s = ei[i]; d = ei[E_EDGES + i]; }
    else             { s = d = i - E_EDGES; }
    int pos = atomicAdd(&g_cur[d], 1);
    g_srt_src[pos] = s;
}

// ---------------- tf32 tensor-core GEMM, cp.async 3-stage -------------------
__device__ __forceinline__ uint32_t f2tf32(float f) {
    uint32_t u;
    asm("cvt.rna.tf32.f32 %0, %1;" : "=r"(u) : "f"(f));
    return u;
}

template <int EPI>
__global__ __launch_bounds__(256) void mma_gemm_kernel(
    const float* __restrict__ A, const float* __restrict__ B,
    const float* __restrict__ bias, float* __restrict__ C,
    int M, int N, int K, int lda, int ldb, int ldc, int koff, float scale)
{
    const int BM = 128, BN = 64, BK = 16;
    __shared__ __align__(16) float As[3][BM][BK + 4];
    __shared__ __align__(16) float Bs[3][BK][BN + 8];

    int tid = threadIdx.x;
    int lane = tid & 31;
    int w = tid >> 5;
    int wm = (w & 3) * 32;
    int wn = (w >> 2) * 32;
    int gID = lane >> 2;
    int tg  = lane & 3;
    int row0 = blockIdx.y * BM, col0 = blockIdx.x * BN;
    int akoff = koff * blockIdx.x;

    int am  = tid >> 2;
    int ak4 = (tid & 3) * 4;
    int bk  = tid >> 4;
    int bn4 = (tid & 15) * 4;

    float acc[2][4][4];
#pragma unroll
    for (int mi = 0; mi < 2; mi++)
#pragma unroll
        for (int ni = 0; ni < 4; ni++)
#pragma unroll
            for (int r = 0; r < 4; r++) acc[mi][ni][r] = 0.f;

    const int niter = K / BK;

#define ISSUE_TILE(IT, BUF)                                                     \
    {                                                                           \
        int kk_ = (IT) * BK;                                                    \
        _Pragma("unroll")                                                       \
        for (int t = 0; t < 2; t++) {                                           \
            int m_ = am + t * 64;                                               \
            int gm_ = row0 + m_;                                                \
            const float* src_ = &A[(long)gm_ * lda + akoff + kk_ + ak4];        \
            uint32_t dst_ = (uint32_t)__cvta_generic_to_shared(&As[BUF][m_][ak4]); \
            int sz_ = (gm_ < M) ? 16 : 0;                                       \
            asm volatile("cp.async.cg.shared.global [%0], [%1], 16, %2;\n"      \
                         :: "r"(dst_), "l"(src_), "r"(sz_));                    \
        }                                                                       \
        {                                                                       \
            const float* src_ = &B[(long)(kk_ + bk) * ldb + col0 + bn4];        \
            uint32_t dst_ = (uint32_t)__cvta_generic_to_shared(&Bs[BUF][bk][bn4]); \
            asm volatile("cp.async.cg.shared.global [%0], [%1], 16, 16;\n"      \
                         :: "r"(dst_), "l"(src_));                              \
        }                                                                       \
        asm volatile("cp.async.commit_group;\n");                               \
    }

    ISSUE_TILE(0, 0);
    if (niter > 1) ISSUE_TILE(1, 1);

    for (int it = 0; it < niter; it++) {
        int buf = it % 3;
        if (it + 1 < niter) {
            asm volatile("cp.async.wait_group 1;\n");
        } else {
            asm volatile("cp.async.wait_group 0;\n");
        }
        __syncthreads();
        if (it + 2 < niter) ISSUE_TILE(it + 2, (it + 2) % 3);

#pragma unroll
        for (int ks = 0; ks < 2; ks++) {
            int k0 = ks * 8;
            uint32_t a[2][4];
#pragma unroll
            for (int mi = 0; mi < 2; mi++) {
                int r = wm + mi * 16;
                a[mi][0] = f2tf32(As[buf][r + gID][k0 + tg]);
                a[mi][1] = f2tf32(As[buf][r + gID + 8][k0 + tg]);
                a[mi][2] = f2tf32(As[buf][r + gID][k0 + tg + 4]);
                a[mi][3] = f2tf32(As[buf][r + gID + 8][k0 + tg + 4]);
            }
#pragma unroll
            for (int ni = 0; ni < 4; ni++) {
                uint32_t b0 = f2tf32(Bs[buf][k0 + tg][wn + ni * 8 + gID]);
                uint32_t b1 = f2tf32(Bs[buf][k0 + tg + 4][wn + ni * 8 + gID]);
#pragma unroll
                for (int mi = 0; mi < 2; mi++) {
                    asm volatile(
                        "mma.sync.aligned.m16n8k8.row.col.f32.tf32.tf32.f32 "
                        "{%0,%1,%2,%3}, {%4,%5,%6,%7}, {%8,%9}, {%0,%1,%2,%3};\n"
                        : "+f"(acc[mi][ni][0]), "+f"(acc[mi][ni][1]),
                          "+f"(acc[mi][ni][2]), "+f"(acc[mi][ni][3])
                        : "r"(a[mi][0]), "r"(a[mi][1]), "r"(a[mi][2]), "r"(a[mi][3]),
                          "r"(b0), "r"(b1));
                }
            }
        }
        // no bottom barrier: buffer (it%3) is only rewritten by tile it+3,
        // issued after the top __syncthreads of iteration it+1.
    }
#undef ISSUE_TILE

#pragma unroll
    for (int mi = 0; mi < 2; mi++) {
#pragma unroll
        for (int ni = 0; ni < 4; ni++) {
            int r = row0 + wm + mi * 16 + gID;
            int cb = col0 + wn + ni * 8 + tg * 2;
            float bv0 = 0.f, bv1 = 0.f;
            if (bias) { bv0 = bias[cb]; bv1 = bias[cb + 1]; }
#pragma unroll
            for (int half = 0; half < 2; half++) {
                int gr = r + half * 8;
                if (gr >= M) continue;
                float v0 = acc[mi][ni][half * 2 + 0] + bv0;
                float v1 = acc[mi][ni][half * 2 + 1] + bv1;
                if (EPI == 1) { v0 *= scale; v1 *= scale; }
                if (EPI == 2) {
                    v0 = 0.5f * v0 * (1.0f + erff(v0 * 0.70710678118654752f));
                    v1 = 0.5f * v1 * (1.0f + erff(v1 * 0.70710678118654752f));
                }
                *reinterpret_cast<float2*>(&C[(long)gr * ldc + cb]) = make_float2(v0, v1);
            }
        }
    }
}

// ---------------- folded attention weights for ALL layers -------------------
__global__ void watt_prep_kernel(const float* __restrict__ Wc,
                                 const float* __restrict__ att_s,
                                 const float* __restrict__ att_d)
{
    int tid = threadIdx.x;
    int k = tid >> 2, j = tid & 3;
    int l = blockIdx.y;
    const float* att = ((blockIdx.x == 0) ? att_s : att_d) + (long)l * NH * CD;
    const float* wr = Wc + (long)l * HID * HC + (long)k * HC + j * CD;
    const float* ar = att + j * CD;
    float s = 0.f;
#pragma unroll 8
    for (int c = 0; c < CD; c++) s = fmaf(wr[c], ar[c], s);
    g_watt[l * HID * 8 + k * 8 + blockIdx.x * 4 + j] = s;
}

// ---------------- scores from h (standalone, layer 0) -----------------------
__global__ void scores_kernel(const float* __restrict__ h,
                              const float* __restrict__ watt)
{
    int n = (blockIdx.x * blockDim.x + threadIdx.x) >> 5;
    if (n >= N_NODES) return;
    int lane = threadIdx.x & 31;
    float2 hv = *reinterpret_cast<const float2*>(&h[(long)n * HID + lane * 2]);
    int k0 = lane * 2;
    float4 s0 = *reinterpret_cast<const float4*>(&watt[k0 * 8]);
    float4 d0 = *reinterpret_cast<const float4*>(&watt[k0 * 8 + 4]);
    float4 s1 = *reinterpret_cast<const float4*>(&watt[k0 * 8 + 8]);
    float4 d1 = *reinterpret_cast<const float4*>(&watt[k0 * 8 + 12]);
    float v[8];
    v[0] = hv.x * s0.x + hv.y * s1.x;
    v[1] = hv.x * s0.y + hv.y * s1.y;
    v[2] = hv.x * s0.z + hv.y * s1.z;
    v[3] = hv.x * s0.w + hv.y * s1.w;
    v[4] = hv.x * d0.x + hv.y * d1.x;
    v[5] = hv.x * d0.y + hv.y * d1.y;
    v[6] = hv.x * d0.z + hv.y * d1.z;
    v[7] = hv.x * d0.w + hv.y * d1.w;
#pragma unroll
    for (int j = 0; j < 8; j++)
#pragma unroll
        for (int o = 16; o > 0; o >>= 1)
            v[j] += __shfl_xor_sync(0xffffffffu, v[j], o);
    if (lane == 0) {
        *reinterpret_cast<float4*>(&g_as[n * 4]) = make_float4(v[0], v[1], v[2], v[3]);
        *reinterpret_cast<float4*>(&g_ad[n * 4]) = make_float4(v[4], v[5], v[6], v[7]);
    }
}

__device__ __forceinline__ float lrelu(float x) { return x > 0.f ? x : 0.2f * x; }

// ------ fused softmax + aggregation (warp per dst, chunked MLP-8 gathers) ---
__global__ __launch_bounds__(256) void agg_fused_kernel(const float* __restrict__ h,
                                                        float* __restrict__ ah)
{
    int d = (blockIdx.x * blockDim.x + threadIdx.x) >> 5;
    if (d >= N_NODES) return;
    int lane = threadIdx.x & 31;
    int beg = g_off[d], end = g_off[d + 1];
    float4 ad = *reinterpret_cast<const float4*>(g_ad + d * 4);

    // pass 1: warp max of as (lrelu monotone)
    float m0 = -INFINITY, m1 = -INFINITY, m2 = -INFINITY, m3 = -INFINITY;
    for (int p = beg + lane; p < end; p += 32) {
        int s = g_srt_src[p];
        float4 as = *reinterpret_cast<const float4*>(g_as + s * 4);
        m0 = fmaxf(m0, as.x); m1 = fmaxf(m1, as.y);
        m2 = fmaxf(m2, as.z); m3 = fmaxf(m3, as.w);
    }
#pragma unroll
    for (int o = 16; o > 0; o >>= 1) {
        m0 = fmaxf(m0, __shfl_xor_sync(0xffffffffu, m0, o));
        m1 = fmaxf(m1, __shfl_xor_sync(0xffffffffu, m1, o));
        m2 = fmaxf(m2, __shfl_xor_sync(0xffffffffu, m2, o));
        m3 = fmaxf(m3, __shfl_xor_sync(0xffffffffu, m3, o));
    }
    m0 = lrelu(m0 + ad.x); m1 = lrelu(m1 + ad.y);
    m2 = lrelu(m2 + ad.z); m3 = lrelu(m3 + ad.w);

    // pass 2: exp + chunked broadcast + MLP-8 gather-FMA
    float2 a0 = make_float2(0.f, 0.f), a1 = a0, a2 = a0, a3 = a0;
    float z0 = 0.f, z1 = 0.f, z2 = 0.f, z3 = 0.f;
    for (int base = beg; base < end; base += 32) {
        int p = base + lane;
        bool valid = p < end;
        int s = valid ? g_srt_src[p] : 0;
        float4 as = *reinterpret_cast<const float4*>(g_as + s * 4);
        float e0 = 0.f, e1 = 0.f, e2 = 0.f, e3 = 0.f;
        if (valid) {
            e0 = expf(lrelu(as.x + ad.x) - m0);
            e1 = expf(lrelu(as.y + ad.y) - m1);
            e2 = expf(lrelu(as.z + ad.z) - m2);
            e3 = expf(lrelu(as.w + ad.w) - m3);
            z0 += e0; z1 += e1; z2 += e2; z3 += e3;
        }
        int nn = min(32, end - base);
        for (int i0 = 0; i0 < nn; i0 += 8) {
            int m = nn - i0;                 // >= 1; cap at 8 via predicates
            int si[8];
            float2 hv[8];
#pragma unroll
            for (int j = 0; j < 8; j++) {
                si[j] = __shfl_sync(0xffffffffu, s, i0 + j);
                if (j < m)
                    hv[j] = *reinterpret_cast<const float2*>(&h[(long)si[j] * HID + lane * 2]);
            }
#pragma unroll
            for (int j = 0; j < 8; j++) {
                if (j < m) {
                    float b0 = __shfl_sync(0xffffffffu, e0, i0 + j);
                    float b1 = __shfl_sync(0xffffffffu, e1, i0 + j);
                    float b2 = __shfl_sync(0xffffffffu, e2, i0 + j);
                    float b3 = __shfl_sync(0xffffffffu, e3, i0 + j);
                    a0.x = fmaf(b0, hv[j].x, a0.x); a0.y = fmaf(b0, hv[j].y, a0.y);
                    a1.x = fmaf(b1, hv[j].x, a1.x); a1.y = fmaf(b1, hv[j].y, a1.y);
                    a2.x = fmaf(b2, hv[j].x, a2.x); a2.y = fmaf(b2, hv[j].y, a2.y);
                    a3.x = fmaf(b3, hv[j].x, a3.x); a3.y = fmaf(b3, hv[j].y, a3.y);
                }
            }
        }
    }
#pragma unroll
    for (int o = 16; o > 0; o >>= 1) {
        z0 += __shfl_xor_sync(0xffffffffu, z0, o);
        z1 += __shfl_xor_sync(0xffffffffu, z1, o);
        z2 += __shfl_xor_sync(0xffffffffu, z2, o);
        z3 += __shfl_xor_sync(0xffffffffu, z3, o);
    }
    float r0 = 1.f / (z0 + 1e-16f), r1 = 1.f / (z1 + 1e-16f);
    float r2 = 1.f / (z2 + 1e-16f), r3 = 1.f / (z3 + 1e-16f);
    a0.x *= r0; a0.y *= r0;
    a1.x *= r1; a1.y *= r1;
    a2.x *= r2; a2.y *= r2;
    a3.x *= r3; a3.y *= r3;
    long basep = (long)d * HC + lane * 2;
    *reinterpret_cast<float2*>(&ah[basep + 0 * CD]) = a0;
    *reinterpret_cast<float2*>(&ah[basep + 1 * CD]) = a1;
    *reinterpret_cast<float2*>(&ah[basep + 2 * CD]) = a2;
    *reinterpret_cast<float2*>(&ah[basep + 3 * CD]) = a3;
}

// ------- layernorm + residual (+ fused next-layer scores) (warp per node) ---
__global__ void ln_kernel(const float* __restrict__ f,
                          const float* __restrict__ gam,
                          const float* __restrict__ bet,
                          float* __restrict__ h,
                          const float* __restrict__ watt)
{
    int node = (blockIdx.x * blockDim.x + threadIdx.x) >> 5;
    if (node >= N_NODES) return;
    int lane = threadIdx.x & 31;
    float v0 = f[(long)node * HID + lane];
    float v1 = f[(long)node * HID + 32 + lane];
    float s = v0 + v1;
#pragma unroll
    for (int o = 16; o > 0; o >>= 1) s += __shfl_xor_sync(0xffffffffu, s, o);
    float mean = s * (1.f / 64.f);
    float d0 = v0 - mean, d1 = v1 - mean;
    float vv = d0 * d0 + d1 * d1;
#pragma unroll
    for (int o = 16; o > 0; o >>= 1) vv += __shfl_xor_sync(0xffffffffu, vv, o);
    float rstd = rsqrtf(vv * (1.f / 64.f) + 1e-5f);
    float o0 = h[(long)node * HID + lane]      + d0 * rstd * gam[lane]      + bet[lane];
    float o1 = h[(long)node * HID + 32 + lane] + d1 * rstd * gam[32 + lane] + bet[32 + lane];
    h[(long)node * HID + lane]      = o0;
    h[(long)node * HID + 32 + lane] = o1;

    if (watt) {
        float4 s0 = *reinterpret_cast<const float4*>(&watt[lane * 8]);
        float4 dd0 = *reinterpret_cast<const float4*>(&watt[lane * 8 + 4]);
        float4 s1 = *reinterpret_cast<const float4*>(&watt[(lane + 32) * 8]);
        float4 dd1 = *reinterpret_cast<const float4*>(&watt[(lane + 32) * 8 + 4]);
        float v[8];
        v[0] = o0 * s0.x + o1 * s1.x;
        v[1] = o0 * s0.y + o1 * s1.y;
        v[2] = o0 * s0.z + o1 * s1.z;
        v[3] = o0 * s0.w + o1 * s1.w;
        v[4] = o0 * dd0.x + o1 * dd1.x;
        v[5] = o0 * dd0.y + o1 * dd1.y;
        v[6] = o0 * dd0.z + o1 * dd1.z;
        v[7] = o0 * dd0.w + o1 * dd1.w;
#pragma unroll
        for (int j = 0; j < 8; j++)
#pragma unroll
            for (int o = 16; o > 0; o >>= 1)
                v[j] += __shfl_xor_sync(0xffffffffu, v[j], o);
        if (lane == 0) {
            *reinterpret_cast<float4*>(&g_as[node * 4]) = make_float4(v[0], v[1], v[2], v[3]);
            *reinterpret_cast<float4*>(&g_ad[node * 4]) = make_float4(v[4], v[5], v[6], v[7]);
        }
    }
}

// ---------------- driver -----------------------------------------------------
extern "C" void kernel_launch(void* const* d_in, const int* in_sizes, int n_in,
                              void* d_out, int out_size)
{
    const float* x     = (const float*)d_in[0];
    const int*   ei    = (const int*)  d_in[1];
    const float* We    = (const float*)d_in[2];
    const float* be    = (const float*)d_in[3];
    const float* Wc    = (const float*)d_in[4];
    const float* att_s = (const float*)d_in[5];
    const float* att_d = (const float*)d_in[6];
    const float* bc    = (const float*)d_in[7];
    const float* W1    = (const float*)d_in[8];
    const float* b1    = (const float*)d_in[9];
    const float* W2    = (const float*)d_in[10];
    const float* b2    = (const float*)d_in[11];
    const float* lng   = (const float*)d_in[12];
    const float* lnb   = (const float*)d_in[13];
    float* h = (float*)d_out;

    float *p_xh, *p_out, *p_f1, *p_watt;
    cudaGetSymbolAddress((void**)&p_xh,   g_xh);
    cudaGetSymbolAddress((void**)&p_out,  g_out);
    cudaGetSymbolAddress((void**)&p_f1,   g_f1);
    cudaGetSymbolAddress((void**)&p_watt, g_watt);

    // ---- folded attention weights for all layers (independent of h) ----
    watt_prep_kernel<<<dim3(2, NL), 256>>>(Wc, att_s, att_d);

    // ---- CSR build (once; reused across layers) ----
    zero_cnt_kernel<<<(N_NODES + 255) / 256, 256>>>();
    hist_kernel<<<(EN + 255) / 256, 256>>>(ei);
    scan1_kernel<<<SCAN_NB, 256>>>();
    scan2_kernel<<<1, 128>>>();
    scan3_kernel<<<SCAN_NB, 256>>>();
    scatter_kernel<<<(EN + 255) / 256, 256>>>(ei);

    const int GY = (N_NODES + 127) / 128;
    const int WG = (N_NODES * 32 + 255) / 256;   // warp-per-node grids

    // ---- embed: h = (x @ We + be) * 8 ----
    mma_gemm_kernel<1><<<dim3(1, GY), 256>>>(x, We, be, h,
                                             N_NODES, HID, IN_DIM,
                                             IN_DIM, HID, HID, 0, 8.0f);
    // scores for layer 0
    scores_kernel<<<WG, 256>>>(h, p_watt);

    for (int l = 0; l < NL; l++) {
        const float* Wc_l = Wc + (long)l * HID * HC;
        // fused softmax + aggregate -> g_xh as ah buffer
        agg_fused_kernel<<<WG, 256>>>(h, p_xh);
        // project per head: out[:, hd*64:+64] = ah[:, hd*64:+64] @ Wc_l[hd] + bc
        mma_gemm_kernel<0><<<dim3(NH, GY), 256>>>(p_xh, Wc_l, bc + l * HC, p_out,
                                                  N_NODES, CD, HID,
                                                  HC, HC, HC, CD, 0.f);
        // f1 = gelu(out @ W1[l] + b1[l])
        mma_gemm_kernel<2><<<dim3(DFF / 64, GY), 256>>>(p_out, W1 + (long)l * HC * DFF,
                                                        b1 + l * DFF, p_f1,
                                                        N_NODES, DFF, HC,
                                                        HC, DFF, DFF, 0, 0.f);
        // f2 = f1 @ W2[l] + b2[l]  (reuse g_xh as f2 buffer)
        mma_gemm_kernel<0><<<dim3(1, GY), 256>>>(p_f1, W2 + (long)l * DFF * HID,
                                                 b2 + l * HID, p_xh,
                                                 N_NODES, HID, DFF,
                                                 DFF, HID, HID, 0, 0.f);
        // h += layernorm(f2); fused scores for next layer
        const float* watt_next = (l + 1 < NL) ? (p_watt + (l + 1) * HID * 8) : nullptr;
        ln_kernel<<<WG, 256>>>(p_xh, lng + l * HID, lnb + l * HID, h, watt_next);
    }
    (void)in_sizes; (void)n_in; (void)out_size;
}